// round 5
// baseline (speedup 1.0000x reference)
#include <cuda_runtime.h>

#define ETA_MIN 0.6931471805599453f
#define ETA_MAX 10.0f

// out[i] = loss[i] > eta ? 0 : 1 - loss[i]/eta,  eta = clamp(eta_value[0], ln2, 10)
// R3 structure (best so far: 4 x float4 per thread, 256 threads, flat tiled grid,
// default-cached loads). Single change this round: streaming stores (__stcs) --
// the output is never re-read, so evict-first writes should cut L2 churn
// against the concurrent read stream.

__device__ __forceinline__ float4 weight4(float4 a, float eta, float inv_eta) {
    float4 r;
    r.x = (a.x > eta) ? 0.0f : fmaf(-a.x, inv_eta, 1.0f);
    r.y = (a.y > eta) ? 0.0f : fmaf(-a.y, inv_eta, 1.0f);
    r.z = (a.z > eta) ? 0.0f : fmaf(-a.z, inv_eta, 1.0f);
    r.w = (a.w > eta) ? 0.0f : fmaf(-a.w, inv_eta, 1.0f);
    return r;
}

__global__ __launch_bounds__(256) void weights_kernel(
    const float4* __restrict__ loss4,
    const float* __restrict__ eta_value,
    float4* __restrict__ out4,
    int n4)
{
    float eta = eta_value[0];
    eta = fminf(fmaxf(eta, ETA_MIN), ETA_MAX);
    float inv_eta = 1.0f / eta;

    // Each block covers 1024 consecutive float4 (64KB in, 64KB out).
    int base = blockIdx.x * (blockDim.x * 4) + threadIdx.x;

    if (base + 3 * 256 < n4) {
        // Hot path: 4 independent LDG.128 front-batched (default cache op).
        float4 a0 = loss4[base];
        float4 a1 = loss4[base + 256];
        float4 a2 = loss4[base + 512];
        float4 a3 = loss4[base + 768];

        __stcs(&out4[base],       weight4(a0, eta, inv_eta));
        __stcs(&out4[base + 256], weight4(a1, eta, inv_eta));
        __stcs(&out4[base + 512], weight4(a2, eta, inv_eta));
        __stcs(&out4[base + 768], weight4(a3, eta, inv_eta));
    } else {
        #pragma unroll
        for (int k = 0; k < 4; k++) {
            int idx = base + k * 256;
            if (idx < n4) {
                float4 a = loss4[idx];
                __stcs(&out4[idx], weight4(a, eta, inv_eta));
            }
        }
    }
}

// Scalar tail for n % 4 != 0 (not hit for N=2^25; kept for generality).
__global__ void weights_tail_kernel(
    const float* __restrict__ loss,
    const float* __restrict__ eta_value,
    float* __restrict__ out,
    int start, int n)
{
    int i = start + blockIdx.x * blockDim.x + threadIdx.x;
    if (i < n) {
        float eta = eta_value[0];
        eta = fminf(fmaxf(eta, ETA_MIN), ETA_MAX);
        float v = loss[i];
        out[i] = (v > eta) ? 0.0f : 1.0f - v / eta;
    }
}

extern "C" void kernel_launch(void* const* d_in, const int* in_sizes, int n_in,
                              void* d_out, int out_size)
{
    const float* loss = (const float*)d_in[0];
    const float* eta_value = (const float*)d_in[1];
    float* out = (float*)d_out;
    int n = in_sizes[0];

    int n4 = n / 4;
    int vec_elems = n4 * 4;

    const int threads = 256;
    const int per_block = threads * 4;  // 1024 float4 per block
    int blocks = (n4 + per_block - 1) / per_block;  // 8192 for N=2^25

    if (blocks > 0) {
        weights_kernel<<<blocks, threads>>>(
            (const float4*)loss, eta_value, (float4*)out, n4);
    }
    int tail = n - vec_elems;
    if (tail > 0) {
        int tb = (tail + 255) / 256;
        weights_tail_kernel<<<tb, 256>>>(loss, eta_value, out, vec_elems, n);
    }
}

// round 6
// speedup vs baseline: 1.0399x; 1.0399x over previous
#include <cuda_runtime.h>

#define ETA_MIN 0.6931471805599453f
#define ETA_MAX 10.0f

// out[i] = loss[i] > eta ? 0 : 1 - loss[i]/eta,  eta = clamp(eta_value[0], ln2, 10)
// Champion structure (R3): 4 independent front-batched LDG.128 per thread,
// flat block-tiled grid, DEFAULT cache operators (.cs regressed both ways).
// Single change vs R3: 512 threads/block (2048 float4 = 256KB i/o per block)
// for better per-block DRAM locality and fewer CTA boundaries.

__device__ __forceinline__ float4 weight4(float4 a, float eta, float inv_eta) {
    float4 r;
    r.x = (a.x > eta) ? 0.0f : fmaf(-a.x, inv_eta, 1.0f);
    r.y = (a.y > eta) ? 0.0f : fmaf(-a.y, inv_eta, 1.0f);
    r.z = (a.z > eta) ? 0.0f : fmaf(-a.z, inv_eta, 1.0f);
    r.w = (a.w > eta) ? 0.0f : fmaf(-a.w, inv_eta, 1.0f);
    return r;
}

__global__ __launch_bounds__(512) void weights_kernel(
    const float4* __restrict__ loss4,
    const float* __restrict__ eta_value,
    float4* __restrict__ out4,
    int n4)
{
    float eta = eta_value[0];
    eta = fminf(fmaxf(eta, ETA_MIN), ETA_MAX);
    float inv_eta = 1.0f / eta;

    const int T = 512;
    int base = blockIdx.x * (T * 4) + threadIdx.x;

    if (base + 3 * T < n4) {
        // Hot path: 4 independent LDG.128 front-batched (default cache op).
        float4 a0 = loss4[base];
        float4 a1 = loss4[base + T];
        float4 a2 = loss4[base + 2 * T];
        float4 a3 = loss4[base + 3 * T];

        out4[base]         = weight4(a0, eta, inv_eta);
        out4[base + T]     = weight4(a1, eta, inv_eta);
        out4[base + 2 * T] = weight4(a2, eta, inv_eta);
        out4[base + 3 * T] = weight4(a3, eta, inv_eta);
    } else {
        #pragma unroll
        for (int k = 0; k < 4; k++) {
            int idx = base + k * T;
            if (idx < n4) {
                float4 a = loss4[idx];
                out4[idx] = weight4(a, eta, inv_eta);
            }
        }
    }
}

// Scalar tail for n % 4 != 0 (not hit for N=2^25; kept for generality).
__global__ void weights_tail_kernel(
    const float* __restrict__ loss,
    const float* __restrict__ eta_value,
    float* __restrict__ out,
    int start, int n)
{
    int i = start + blockIdx.x * blockDim.x + threadIdx.x;
    if (i < n) {
        float eta = eta_value[0];
        eta = fminf(fmaxf(eta, ETA_MIN), ETA_MAX);
        float v = loss[i];
        out[i] = (v > eta) ? 0.0f : 1.0f - v / eta;
    }
}

extern "C" void kernel_launch(void* const* d_in, const int* in_sizes, int n_in,
                              void* d_out, int out_size)
{
    const float* loss = (const float*)d_in[0];
    const float* eta_value = (const float*)d_in[1];
    float* out = (float*)d_out;
    int n = in_sizes[0];

    int n4 = n / 4;
    int vec_elems = n4 * 4;

    const int threads = 512;
    const int per_block = threads * 4;  // 2048 float4 per block
    int blocks = (n4 + per_block - 1) / per_block;  // 4096 for N=2^25

    if (blocks > 0) {
        weights_kernel<<<blocks, threads>>>(
            (const float4*)loss, eta_value, (float4*)out, n4);
    }
    int tail = n - vec_elems;
    if (tail > 0) {
        int tb = (tail + 255) / 256;
        weights_tail_kernel<<<tb, 256>>>(loss, eta_value, out, vec_elems, n);
    }
}